// round 10
// baseline (speedup 1.0000x reference)
#include <cuda_runtime.h>

#define Dd     3
#define HID    64
#define WIDTH  64
#define BATCH  500000
#define BLOCKP (Dd * WIDTH)         // 192
#define P3N    (3 * BLOCKP + WIDTH) // 640

#define TPB    128
#define EPT    4                     // 2 f32x2 pairs per thread
#define NPAIR  2
#define GRID   ((BATCH / EPT + TPB - 1) / TPB)   // 977

// -2 * log2(e): folded into W,B of odd-j params by the hypernet
#define NEG2LOG2E (-2.8853900817779268f)

typedef unsigned long long ull;

// Params, packed-duplicated for f32x2 math. Per hidden unit j, 4 float4s:
//  [4j+0] = {W0,W0,W1,W1}      (odd j: W scaled by -2log2e)
//  [4j+1] = {W2,W2,B,B}        (odd j: scaled by -2log2e)
//  [4j+2] = {U0/64,U0/64,U1/64,U1/64}
//  [4j+3] = {U2/64,U2/64,wu/64,wu/64}
__device__ float4 g_p4[4 * WIDTH];

// ---------------------------------------------------------------------------
// helpers
// ---------------------------------------------------------------------------
__device__ __forceinline__ ull ffma2(ull a, ull b, ull c) {
    ull d;
    asm("fma.rn.f32x2 %0, %1, %2, %3;" : "=l"(d) : "l"(a), "l"(b), "l"(c));
    return d;
}
__device__ __forceinline__ ull fmul2(ull a, ull b) {
    ull d;
    asm("mul.rn.f32x2 %0, %1, %2;" : "=l"(d) : "l"(a), "l"(b));
    return d;
}
__device__ __forceinline__ ull pack2(float lo, float hi) {
    ull d;
    asm("mov.b64 %0, {%1, %2};" : "=l"(d) : "f"(lo), "f"(hi));
    return d;
}
__device__ __forceinline__ void unpack2(ull v, float& lo, float& hi) {
    asm("mov.b64 {%0, %1}, %2;" : "=f"(lo), "=f"(hi) : "l"(v));
}
__device__ __forceinline__ float tanha(float x) {
    float r;
    asm("tanh.approx.f32 %0, %1;" : "=f"(r) : "f"(x));
    return r;
}
__device__ __forceinline__ float ex2f(float x) {
    float r;
    asm("ex2.approx.f32 %0, %1;" : "=f"(r) : "f"(x));
    return r;
}

// Vectorized tanh from PRE-SCALED packed input ps2 = -2log2e * pre (per lane).
// Per lane: u = -|ps| (FMNMX), v = 2^u = e^{-2|pre|} (MUFU ex2, full rate).
// tanh(|pre|) = 1 + v*q(v), q = deg-5 poly of -2/(1+v) on [0,1]  (f32x2 Horner).
// sign(pre) = -sign(ps): restored with one LOP3 per lane.
// Max abs err ~5e-5 (validated R9: rel_err 1.8e-5 at f=0.5).
__device__ __forceinline__ ull polytanh2(ull ps2) {
    float plo, phi;
    unpack2(ps2, plo, phi);
    float vlo = ex2f(fminf(plo, -plo));
    float vhi = ex2f(fminf(phi, -phi));
    ull v2 = pack2(vlo, vhi);
    ull q;
    q = ffma2(v2, pack2( 0.21530624f,  0.21530624f), pack2(-0.85199872f, -0.85199872f));
    q = ffma2(q, v2, pack2( 1.55559104f,  1.55559104f));
    q = ffma2(q, v2, pack2(-1.91217760f, -1.91217760f));
    q = ffma2(q, v2, pack2( 1.99325208f,  1.99325208f));
    q = ffma2(q, v2, pack2(-1.99991232f, -1.99991232f));
    ull g2 = ffma2(v2, q, pack2(1.0f, 1.0f));
    float glo, ghi;
    unpack2(g2, glo, ghi);
    unsigned hlo = (__float_as_uint(glo) & 0x7fffffffu) |
                   (~__float_as_uint(plo) & 0x80000000u);
    unsigned hhi = (__float_as_uint(ghi) & 0x7fffffffu) |
                   (~__float_as_uint(phi) & 0x80000000u);
    return pack2(__uint_as_float(hlo), __uint_as_float(hhi));
}

// ---------------------------------------------------------------------------
// Kernel 1: hypernet, 4 blocks. Block b produces j in [16b, 16b+16).
// PDL: triggers launch completion immediately.
// ---------------------------------------------------------------------------
__global__ void __launch_bounds__(256)
hyper_kernel(const float* __restrict__ t,
             const float* __restrict__ fc1_w,
             const float* __restrict__ fc1_b,
             const float* __restrict__ fc2_w,
             const float* __restrict__ fc2_b,
             const float* __restrict__ fc3_w,
             const float* __restrict__ fc3_b)
{
#if __CUDA_ARCH__ >= 900
    cudaTriggerProgrammaticLaunchCompletion();
#endif

    __shared__ float p1[HID];
    __shared__ float p2[HID];
    __shared__ float p3loc[160];

    const int tid = threadIdx.x;
    const int b   = blockIdx.x;

    // stage 1
    if (tid < HID) {
        p1[tid] = tanhf(t[0] * fc1_w[tid] + fc1_b[tid]);
    }
    __syncthreads();

    // stage 2
    if (tid < HID) {
        const float4* row = reinterpret_cast<const float4*>(fc2_w + tid * HID);
        float a0 = 0.f, a1 = 0.f, a2 = 0.f, a3 = 0.f;
        #pragma unroll
        for (int i = 0; i < 16; i++) {
            float4 r = row[i];
            const float* pp = p1 + 4 * i;
            a0 = fmaf(r.x, pp[0], a0);
            a1 = fmaf(r.y, pp[1], a1);
            a2 = fmaf(r.z, pp[2], a2);
            a3 = fmaf(r.w, pp[3], a3);
        }
        p2[tid] = tanhf((a0 + a1) + (a2 + a3) + fc2_b[tid]);
    }
    __syncthreads();

    // stage 3: the 160 fc3 rows this block's j-slice needs.
    if (tid < 160) {
        int grow;
        if      (tid < 48)  grow = 48 * b + tid;
        else if (tid < 96)  grow = BLOCKP + 48 * b + (tid - 48);
        else if (tid < 144) grow = 2 * BLOCKP + 48 * b + (tid - 96);
        else                grow = 3 * BLOCKP + 16 * b + (tid - 144);

        const float4* row = reinterpret_cast<const float4*>(fc3_w + grow * HID);
        float a0 = 0.f, a1 = 0.f, a2 = 0.f, a3 = 0.f;
        #pragma unroll
        for (int i = 0; i < 16; i++) {
            float4 r = row[i];
            const float* pp = p2 + 4 * i;
            a0 = fmaf(r.x, pp[0], a0);
            a1 = fmaf(r.y, pp[1], a1);
            a2 = fmaf(r.z, pp[2], a2);
            a3 = fmaf(r.w, pp[3], a3);
        }
        p3loc[tid] = (a0 + a1) + (a2 + a3) + fc3_b[grow];
    }
    __syncthreads();

    // assemble this block's 16 j's; fold 1/WIDTH into U and wu.
    // Odd j: additionally scale W,B by -2log2e for the polytanh path.
    const float inv = 1.0f / (float)WIDTH;
    if (tid < 16) {
        const int j = 16 * b + tid;
        float w[3], u[3];
        #pragma unroll
        for (int d = 0; d < 3; d++) {
            w[d] = p3loc[3 * tid + d];
            float ur = p3loc[48 + 3 * tid + d];
            float g  = p3loc[96 + 3 * tid + d];
            float sg = 1.0f / (1.0f + expf(-g));
            u[d] = ur * sg * inv;
        }
        float wu = fmaf(w[0], u[0], fmaf(w[1], u[1], w[2] * u[2]));
        float bb = p3loc[144 + tid];
        const float m = (j & 1) ? NEG2LOG2E : 1.0f;
        float w0 = w[0] * m, w1 = w[1] * m, w2 = w[2] * m, bs = bb * m;
        g_p4[4 * j + 0] = make_float4(w0, w0, w1, w1);
        g_p4[4 * j + 1] = make_float4(w2, w2, bs, bs);
        g_p4[4 * j + 2] = make_float4(u[0], u[0], u[1], u[1]);
        g_p4[4 * j + 3] = make_float4(u[2], u[2], wu,  wu);
    }
}

// ---------------------------------------------------------------------------
// Kernel 2: main batch kernel. 4 elements/thread = 2 f32x2 pairs.
// Even j: tanh.approx (MUFU-heavy).  Odd j: ex2 + f32x2 poly (FMA-heavy).
// ---------------------------------------------------------------------------
__global__ void __launch_bounds__(TPB, 6)
cnf_kernel(const float* __restrict__ z, float* __restrict__ out)
{
    __shared__ __align__(16) float4 sp4[4 * WIDTH];
    __shared__ float sS;

    const int tid  = threadIdx.x;
    const int base = (blockIdx.x * TPB + tid) * EPT;
    const bool active = (base < BATCH);   // BATCH % 4 == 0

    // preload z while hyper_kernel may still be running
    float4 a0, a1, a2;
    if (active) {
        const float4* z4 = reinterpret_cast<const float4*>(z + (size_t)base * 3);
        a0 = z4[0]; a1 = z4[1]; a2 = z4[2];
    }

#if __CUDA_ARCH__ >= 900
    cudaGridDependencySynchronize();
#endif

    sp4[tid]       = g_p4[tid];
    sp4[tid + TPB] = g_p4[tid + TPB];
    __syncthreads();

    // S = sum_j wu'/64 — warp 0 computes once per block
    if (tid < 32) {
        float s = sp4[4 * tid + 3].z + sp4[4 * (tid + 32) + 3].z;
        #pragma unroll
        for (int off = 16; off > 0; off >>= 1)
            s += __shfl_xor_sync(0xffffffffu, s, off);
        if (tid == 0) sS = s;
    }
    __syncthreads();

    if (!active) return;
    const float S = sS;

    // pack into f32x2 pairs: pair0 = elems {0,1}, pair1 = elems {2,3}
    ull zx2[NPAIR], zy2[NPAIR], zz2[NPAIR];
    zx2[0] = pack2(a0.x, a0.w);
    zy2[0] = pack2(a0.y, a1.x);
    zz2[0] = pack2(a0.z, a1.y);
    zx2[1] = pack2(a1.z, a2.y);
    zy2[1] = pack2(a1.w, a2.z);
    zz2[1] = pack2(a2.x, a2.w);

    ull d0[NPAIR], d1[NPAIR], d2[NPAIR], hw[NPAIR];
    #pragma unroll
    for (int p = 0; p < NPAIR; p++) { d0[p] = 0; d1[p] = 0; d2[p] = 0; hw[p] = 0; }

    const ulonglong2* spp = reinterpret_cast<const ulonglong2*>(sp4);

    #pragma unroll 4
    for (int j = 0; j < WIDTH; j += 2) {
        // ---- even j: tanh.approx path (MUFU) ----
        {
            const ulonglong2 q0 = spp[4 * j + 0];
            const ulonglong2 q1 = spp[4 * j + 1];
            const ulonglong2 q2 = spp[4 * j + 2];
            const ulonglong2 q3 = spp[4 * j + 3];
            #pragma unroll
            for (int p = 0; p < NPAIR; p++) {
                ull pre = ffma2(zz2[p], q1.x, q1.y);
                pre = ffma2(zy2[p], q0.y, pre);
                pre = ffma2(zx2[p], q0.x, pre);
                float plo, phi;
                unpack2(pre, plo, phi);
                ull h2 = pack2(tanha(plo), tanha(phi));
                d0[p] = ffma2(h2, q2.x, d0[p]);
                d1[p] = ffma2(h2, q2.y, d1[p]);
                d2[p] = ffma2(h2, q3.x, d2[p]);
                ull hh = fmul2(h2, h2);
                hw[p] = ffma2(hh, q3.y, hw[p]);
            }
        }
        // ---- odd j: ex2 + f32x2 poly path (FMA), params pre-scaled ----
        {
            const ulonglong2 q0 = spp[4 * (j + 1) + 0];
            const ulonglong2 q1 = spp[4 * (j + 1) + 1];
            const ulonglong2 q2 = spp[4 * (j + 1) + 2];
            const ulonglong2 q3 = spp[4 * (j + 1) + 3];
            #pragma unroll
            for (int p = 0; p < NPAIR; p++) {
                ull pre = ffma2(zz2[p], q1.x, q1.y);   // = -2log2e * (z.W + B)
                pre = ffma2(zy2[p], q0.y, pre);
                pre = ffma2(zx2[p], q0.x, pre);
                ull h2 = polytanh2(pre);
                d0[p] = ffma2(h2, q2.x, d0[p]);
                d1[p] = ffma2(h2, q2.y, d1[p]);
                d2[p] = ffma2(h2, q3.x, d2[p]);
                ull hh = fmul2(h2, h2);
                hw[p] = ffma2(hh, q3.y, hw[p]);
            }
        }
    }

    // epilogue (/WIDTH already folded into params)
    float od[12], lp[4];
    #pragma unroll
    for (int p = 0; p < NPAIR; p++) {
        float a, b;
        unpack2(d0[p], a, b); od[6 * p + 0] = a; od[6 * p + 3] = b;
        unpack2(d1[p], a, b); od[6 * p + 1] = a; od[6 * p + 4] = b;
        unpack2(d2[p], a, b); od[6 * p + 2] = a; od[6 * p + 5] = b;
        unpack2(hw[p], a, b);
        lp[2 * p + 0] = a - S;
        lp[2 * p + 1] = b - S;
    }

    float4* o = reinterpret_cast<float4*>(out + (size_t)base * 3);
    o[0] = make_float4(od[0], od[1], od[2],  od[3]);
    o[1] = make_float4(od[4], od[5], od[6],  od[7]);
    o[2] = make_float4(od[8], od[9], od[10], od[11]);

    *reinterpret_cast<float4*>(out + (size_t)(3 * BATCH) + base) =
        make_float4(lp[0], lp[1], lp[2], lp[3]);
}

// ---------------------------------------------------------------------------
// Launch: hyper, then cnf with programmatic stream serialization (PDL).
// ---------------------------------------------------------------------------
extern "C" void kernel_launch(void* const* d_in, const int* in_sizes, int n_in,
                              void* d_out, int out_size)
{
    const float* t     = (const float*)d_in[0];
    const float* z     = (const float*)d_in[1];
    // d_in[2] = logp_z (unused)
    const float* fc1_w = (const float*)d_in[3];
    const float* fc1_b = (const float*)d_in[4];
    const float* fc2_w = (const float*)d_in[5];
    const float* fc2_b = (const float*)d_in[6];
    const float* fc3_w = (const float*)d_in[7];
    const float* fc3_b = (const float*)d_in[8];
    float* out = (float*)d_out;

    hyper_kernel<<<4, 256>>>(t, fc1_w, fc1_b, fc2_w, fc2_b, fc3_w, fc3_b);

    cudaLaunchConfig_t cfg = {};
    cfg.gridDim  = dim3(GRID, 1, 1);
    cfg.blockDim = dim3(TPB, 1, 1);
    cfg.dynamicSmemBytes = 0;
    cudaLaunchAttribute attrs[1];
    attrs[0].id = cudaLaunchAttributeProgrammaticStreamSerialization;
    attrs[0].val.programmaticStreamSerializationAllowed = 1;
    cfg.attrs = attrs;
    cfg.numAttrs = 1;
    cudaLaunchKernelEx(&cfg, cnf_kernel, z, out);
}

// round 11
// speedup vs baseline: 1.8765x; 1.8765x over previous
#include <cuda_runtime.h>

#define Dd     3
#define HID    64
#define WIDTH  64
#define BATCH  500000
#define BLOCKP (Dd * WIDTH)         // 192
#define P3N    (3 * BLOCKP + WIDTH) // 640

#define TPB    128
#define EPT    4                     // 2 f32x2 pairs per thread
#define NPAIR  2
#define GRID   ((BATCH / EPT + TPB - 1) / TPB)   // 977

typedef unsigned long long ull;

// Params, packed-duplicated for f32x2 math. Per hidden unit j, 4 float4s:
//  [4j+0] = {W0,W0,W1,W1}
//  [4j+1] = {W2,W2,B,B}
//  [4j+2] = {U0/64,U0/64,U1/64,U1/64}
//  [4j+3] = {U2/64,U2/64,wu/64,wu/64}
__device__ float4 g_p4[4 * WIDTH];

// ---------------------------------------------------------------------------
// helpers
// ---------------------------------------------------------------------------
__device__ __forceinline__ ull ffma2(ull a, ull b, ull c) {
    ull d;
    asm("fma.rn.f32x2 %0, %1, %2, %3;" : "=l"(d) : "l"(a), "l"(b), "l"(c));
    return d;
}
__device__ __forceinline__ ull fmul2(ull a, ull b) {
    ull d;
    asm("mul.rn.f32x2 %0, %1, %2;" : "=l"(d) : "l"(a), "l"(b));
    return d;
}
__device__ __forceinline__ ull pack2(float lo, float hi) {
    ull d;
    asm("mov.b64 %0, {%1, %2};" : "=l"(d) : "f"(lo), "f"(hi));
    return d;
}
__device__ __forceinline__ void unpack2(ull v, float& lo, float& hi) {
    asm("mov.b64 {%0, %1}, %2;" : "=f"(lo), "=f"(hi) : "l"(v));
}
__device__ __forceinline__ float tanha(float x) {
    float r;
    asm("tanh.approx.f32 %0, %1;" : "=f"(r) : "f"(x));
    return r;
}

// ---------------------------------------------------------------------------
// Kernel 1: hypernet, 4 blocks. Block b produces j in [16b, 16b+16).
// ALL global loads are issued into registers at kernel entry, so the block
// pays ~one memory latency total instead of three serialized stage latencies.
// PDL: triggers launch completion immediately.
// ---------------------------------------------------------------------------
__global__ void __launch_bounds__(256)
hyper_kernel(const float* __restrict__ t,
             const float* __restrict__ fc1_w,
             const float* __restrict__ fc1_b,
             const float* __restrict__ fc2_w,
             const float* __restrict__ fc2_b,
             const float* __restrict__ fc3_w,
             const float* __restrict__ fc3_b)
{
#if __CUDA_ARCH__ >= 900
    cudaTriggerProgrammaticLaunchCompletion();
#endif

    __shared__ float p1[HID];
    __shared__ float p2[HID];
    __shared__ float p3loc[160];

    const int tid = threadIdx.x;
    const int b   = blockIdx.x;

    // ---- issue ALL global loads up front (independent of each other) ----
    // stage-1 scalars (tid < 64)
    float tv = 0.f, w1v = 0.f, b1v = 0.f, b2v = 0.f;
    if (tid < HID) {
        tv  = t[0];
        w1v = fc1_w[tid];
        b1v = fc1_b[tid];
        b2v = fc2_b[tid];
    }
    // stage-2 row (tid < 64): fc2_w row into 16 float4 regs
    float4 r2[16];
    if (tid < HID) {
        const float4* row = reinterpret_cast<const float4*>(fc2_w + tid * HID);
        #pragma unroll
        for (int i = 0; i < 16; i++) r2[i] = row[i];
    }
    // stage-3 row (tid < 160): fc3_w row into 16 float4 regs + its bias
    int grow = 0;
    float4 r3[16];
    float b3v = 0.f;
    if (tid < 160) {
        if      (tid < 48)  grow = 48 * b + tid;
        else if (tid < 96)  grow = BLOCKP + 48 * b + (tid - 48);
        else if (tid < 144) grow = 2 * BLOCKP + 48 * b + (tid - 96);
        else                grow = 3 * BLOCKP + 16 * b + (tid - 144);
        const float4* row = reinterpret_cast<const float4*>(fc3_w + grow * HID);
        #pragma unroll
        for (int i = 0; i < 16; i++) r3[i] = row[i];
        b3v = fc3_b[grow];
    }

    // ---- stage 1 ----
    if (tid < HID) {
        p1[tid] = tanhf(tv * w1v + b1v);
    }
    __syncthreads();

    // ---- stage 2 (row already in registers) ----
    if (tid < HID) {
        float a0 = 0.f, a1 = 0.f, a2 = 0.f, a3 = 0.f;
        #pragma unroll
        for (int i = 0; i < 16; i++) {
            const float* pp = p1 + 4 * i;
            a0 = fmaf(r2[i].x, pp[0], a0);
            a1 = fmaf(r2[i].y, pp[1], a1);
            a2 = fmaf(r2[i].z, pp[2], a2);
            a3 = fmaf(r2[i].w, pp[3], a3);
        }
        p2[tid] = tanhf((a0 + a1) + (a2 + a3) + b2v);
    }
    __syncthreads();

    // ---- stage 3 (row already in registers) ----
    if (tid < 160) {
        float a0 = 0.f, a1 = 0.f, a2 = 0.f, a3 = 0.f;
        #pragma unroll
        for (int i = 0; i < 16; i++) {
            const float* pp = p2 + 4 * i;
            a0 = fmaf(r3[i].x, pp[0], a0);
            a1 = fmaf(r3[i].y, pp[1], a1);
            a2 = fmaf(r3[i].z, pp[2], a2);
            a3 = fmaf(r3[i].w, pp[3], a3);
        }
        p3loc[tid] = (a0 + a1) + (a2 + a3) + b3v;
    }
    __syncthreads();

    // ---- assemble this block's 16 j's; fold 1/WIDTH into U and wu ----
    const float inv = 1.0f / (float)WIDTH;
    if (tid < 16) {
        const int j = 16 * b + tid;
        float w[3], u[3];
        #pragma unroll
        for (int d = 0; d < 3; d++) {
            w[d] = p3loc[3 * tid + d];
            float ur = p3loc[48 + 3 * tid + d];
            float g  = p3loc[96 + 3 * tid + d];
            float sg = 1.0f / (1.0f + expf(-g));
            u[d] = ur * sg * inv;
        }
        float wu = fmaf(w[0], u[0], fmaf(w[1], u[1], w[2] * u[2]));
        float bb = p3loc[144 + tid];
        g_p4[4 * j + 0] = make_float4(w[0], w[0], w[1], w[1]);
        g_p4[4 * j + 1] = make_float4(w[2], w[2], bb,  bb);
        g_p4[4 * j + 2] = make_float4(u[0], u[0], u[1], u[1]);
        g_p4[4 * j + 3] = make_float4(u[2], u[2], wu,  wu);
    }
}

// ---------------------------------------------------------------------------
// Kernel 2: main batch kernel (R8 configuration — best measured, unchanged).
// 4 elements/thread = 2 f32x2 pairs; tanh.approx; depth-1 param pipeline.
// PDL consumer: preloads z, then grid-dep-sync before reading g_p4.
// ---------------------------------------------------------------------------
__global__ void __launch_bounds__(TPB, 6)
cnf_kernel(const float* __restrict__ z, float* __restrict__ out)
{
    __shared__ __align__(16) float4 sp4[4 * WIDTH];
    __shared__ float sS;

    const int tid  = threadIdx.x;
    const int base = (blockIdx.x * TPB + tid) * EPT;
    const bool active = (base < BATCH);   // BATCH % 4 == 0: all-or-nothing

    // preload z while hyper_kernel may still be running
    float4 a0, a1, a2;
    if (active) {
        const float4* z4 = reinterpret_cast<const float4*>(z + (size_t)base * 3);
        a0 = z4[0]; a1 = z4[1]; a2 = z4[2];
    }

#if __CUDA_ARCH__ >= 900
    cudaGridDependencySynchronize();
#endif

    // params global -> shared (256 entries, 2 per thread)
    sp4[tid]       = g_p4[tid];
    sp4[tid + TPB] = g_p4[tid + TPB];
    __syncthreads();

    // S = sum_j wu'/64 — warp 0 computes once per block
    if (tid < 32) {
        float s = sp4[4 * tid + 3].z + sp4[4 * (tid + 32) + 3].z;
        #pragma unroll
        for (int off = 16; off > 0; off >>= 1)
            s += __shfl_xor_sync(0xffffffffu, s, off);
        if (tid == 0) sS = s;
    }
    __syncthreads();

    if (!active) return;
    const float S = sS;

    // pack into f32x2 pairs: pair0 = elems {0,1}, pair1 = elems {2,3}
    ull zx2[NPAIR], zy2[NPAIR], zz2[NPAIR];
    zx2[0] = pack2(a0.x, a0.w);
    zy2[0] = pack2(a0.y, a1.x);
    zz2[0] = pack2(a0.z, a1.y);
    zx2[1] = pack2(a1.z, a2.y);
    zy2[1] = pack2(a1.w, a2.z);
    zz2[1] = pack2(a2.x, a2.w);

    ull d0[NPAIR], d1[NPAIR], d2[NPAIR], hw[NPAIR];
    #pragma unroll
    for (int p = 0; p < NPAIR; p++) { d0[p] = 0; d1[p] = 0; d2[p] = 0; hw[p] = 0; }

    const ulonglong2* spp = reinterpret_cast<const ulonglong2*>(sp4);

    // software-pipelined j loop: prefetch j+1 params while computing j
    ulonglong2 c0 = spp[0], c1 = spp[1], c2 = spp[2], c3 = spp[3];

    #pragma unroll 8
    for (int j = 0; j < WIDTH; j++) {
        const int jn = (j + 1) & (WIDTH - 1);
        ulonglong2 n0 = spp[4 * jn + 0];
        ulonglong2 n1 = spp[4 * jn + 1];
        ulonglong2 n2 = spp[4 * jn + 2];
        ulonglong2 n3 = spp[4 * jn + 3];

        #pragma unroll
        for (int p = 0; p < NPAIR; p++) {
            ull pre = ffma2(zz2[p], c1.x, c1.y);
            pre = ffma2(zy2[p], c0.y, pre);
            pre = ffma2(zx2[p], c0.x, pre);
            float plo, phi;
            unpack2(pre, plo, phi);
            ull h2 = pack2(tanha(plo), tanha(phi));
            d0[p] = ffma2(h2, c2.x, d0[p]);
            d1[p] = ffma2(h2, c2.y, d1[p]);
            d2[p] = ffma2(h2, c3.x, d2[p]);
            ull hh = fmul2(h2, h2);
            hw[p] = ffma2(hh, c3.y, hw[p]);
        }

        c0 = n0; c1 = n1; c2 = n2; c3 = n3;
    }

    // epilogue (/WIDTH already folded into params)
    float od[12], lp[4];
    #pragma unroll
    for (int p = 0; p < NPAIR; p++) {
        float a, b;
        unpack2(d0[p], a, b); od[6 * p + 0] = a; od[6 * p + 3] = b;
        unpack2(d1[p], a, b); od[6 * p + 1] = a; od[6 * p + 4] = b;
        unpack2(d2[p], a, b); od[6 * p + 2] = a; od[6 * p + 5] = b;
        unpack2(hw[p], a, b);
        lp[2 * p + 0] = a - S;
        lp[2 * p + 1] = b - S;
    }

    float4* o = reinterpret_cast<float4*>(out + (size_t)base * 3);
    o[0] = make_float4(od[0], od[1], od[2],  od[3]);
    o[1] = make_float4(od[4], od[5], od[6],  od[7]);
    o[2] = make_float4(od[8], od[9], od[10], od[11]);

    *reinterpret_cast<float4*>(out + (size_t)(3 * BATCH) + base) =
        make_float4(lp[0], lp[1], lp[2], lp[3]);
}

// ---------------------------------------------------------------------------
// Launch: hyper, then cnf with programmatic stream serialization (PDL).
// ---------------------------------------------------------------------------
extern "C" void kernel_launch(void* const* d_in, const int* in_sizes, int n_in,
                              void* d_out, int out_size)
{
    const float* t     = (const float*)d_in[0];
    const float* z     = (const float*)d_in[1];
    // d_in[2] = logp_z (unused)
    const float* fc1_w = (const float*)d_in[3];
    const float* fc1_b = (const float*)d_in[4];
    const float* fc2_w = (const float*)d_in[5];
    const float* fc2_b = (const float*)d_in[6];
    const float* fc3_w = (const float*)d_in[7];
    const float* fc3_b = (const float*)d_in[8];
    float* out = (float*)d_out;

    hyper_kernel<<<4, 256>>>(t, fc1_w, fc1_b, fc2_w, fc2_b, fc3_w, fc3_b);

    cudaLaunchConfig_t cfg = {};
    cfg.gridDim  = dim3(GRID, 1, 1);
    cfg.blockDim = dim3(TPB, 1, 1);
    cfg.dynamicSmemBytes = 0;
    cudaLaunchAttribute attrs[1];
    attrs[0].id = cudaLaunchAttributeProgrammaticStreamSerialization;
    attrs[0].val.programmaticStreamSerializationAllowed = 1;
    cfg.attrs = attrs;
    cfg.numAttrs = 1;
    cudaLaunchKernelEx(&cfg, cnf_kernel, z, out);
}